// round 9
// baseline (speedup 1.0000x reference)
#include <cuda_runtime.h>
#include <cuda_fp16.h>

// Problem constants (fixed shapes from reference):
//   x:          [16,64,64,256] fp32  -> N_ROWS=65536 rows of D_DIM=256
//   dictionary: [256,1024]     fp32  -> D_DIM x K_CODES
// Output: q_st (16777216 fp32) followed by loss (1 fp32).
//
// CORRECTNESS-CRITICAL (validated R6+R8, rel_err 1.744e-6, zero argmin flips):
//   fp16 screen (fold to fp32 every 16 d-steps) -> top-3 candidates/thread
//   (48/row) -> EXACT fp32 reference arithmetic replayed on candidates:
//   sim = sequential fmaf chain over d=0..255; t1 = fl(nf + c_k);
//   v = fl(t1 - fl(2*sim)); first-index ties via packed (bits<<32|code)
//   atomicMin. Do NOT alter refine-path order/roundings, the fold-16
//   granularity, or NCAND.
// This round is a PERF-ONLY restructure of the screen: converts hoisted out
// of the inner loop (sAh pre-converted once), 512 threads (4 warps/SMSP for
// latency hiding), smaller per-thread state (regs 217 -> ~110).
#define D_DIM   256
#define K_CODES 1024
#define N_ROWS  65536

#define MTILE   128
#define NTILE   128
#define KCHUNK  32
#define ASTRIDE 260          // fp32 x-tile row stride
#define THREADS 512
#define NCHUNK  64           // (1024/128 tiles) * (256/32 d-chunks)
#define NCAND   3
#define CPR     (16 * NCAND)     // 48 candidates per row
#define TOTC    (MTILE * CPR)    // 6144 per CTA

// SMEM byte offsets (total 229376 <= 227KB limit)
#define OFF_SA    0                        // 128*260*4      = 133120
#define OFF_SAH   133120                   // 128*256*2      =  65536
#define OFF_SBH   198656                   // 2*32*128*2     =  16384
#define OFF_CAND  215040                   // 6144*2 (u16)   =  12288
#define OFF_BEST  227328                   // 128*8  (u64)   =   1024
#define OFF_NF    228352                   // 128*4          =    512
#define OFF_IDX   228864                   // 128*4          =    512
#define SMEM_BYTES 229376

// Scratch (no cudaMalloc): dictT fp32 (refine/gather), dict half (screen),
// code norms, loss accumulator.
__device__ float  g_dictT[K_CODES * D_DIM];
__device__ __half g_dictH[D_DIM * K_CODES];
__device__ float  g_c[K_CODES];
__device__ double g_loss;

// ---------------------------------------------------------------------------
// Kernel 1a: smem-tiled transpose dict[d][k] -> g_dictT[k][d] (coalesced both
// sides) for the refine chains and the epilogue gather.
// ---------------------------------------------------------------------------
__global__ void vq_transpose(const float* __restrict__ dict) {
    __shared__ float tile[32][33];
    const int kb = blockIdx.x * 32;
    const int db = blockIdx.y * 32;
    const int tx = threadIdx.x & 31;
    const int ty = threadIdx.x >> 5;
    #pragma unroll
    for (int r = ty; r < 32; r += 8)
        tile[r][tx] = dict[(size_t)(db + r) * K_CODES + kb + tx];
    __syncthreads();
    #pragma unroll
    for (int r = ty; r < 32; r += 8)
        g_dictT[(size_t)(kb + r) * D_DIM + db + tx] = tile[tx][r];
}

// ---------------------------------------------------------------------------
// Kernel 1b: half copy of dict in [d][k] layout for the HFMA2 screen.
// ---------------------------------------------------------------------------
__global__ void vq_tohalf(const float* __restrict__ dict) {
    int e = blockIdx.x * blockDim.x + threadIdx.x;
    if (e < D_DIM * K_CODES) g_dictH[e] = __float2half_rn(dict[e]);
}

// ---------------------------------------------------------------------------
// Kernel 1c: c_k = sum_d fl(d*d), SEQUENTIAL fp32 adds in d order (load-
// bearing for the argmin grid). Zero loss accumulator.
// ---------------------------------------------------------------------------
__global__ void vq_norms(const float* __restrict__ dict) {
    int k = blockIdx.x * blockDim.x + threadIdx.x;
    if (k == 0) g_loss = 0.0;
    if (k < K_CODES) {
        float c = 0.f;
        for (int d = 0; d < D_DIM; ++d) {
            float v = dict[(size_t)d * K_CODES + k];
            c = __fadd_rn(c, __fmul_rn(v, v));         // no FMA contraction
        }
        g_c[k] = c;
    }
}

// ---------------------------------------------------------------------------
// Kernel 2 (512 threads): screen -> refine -> epilogue.
// Screen thread map: j = t&15 owns 8 codes (4 half2 pairs) of the 128-code
// tile; i = t>>4 (0..31) owns rows {i, i+32, i+64, i+96}. No converts in the
// hot loop: a comes from pre-converted sAh via LDS.U16 + half2half2.
// ---------------------------------------------------------------------------
__global__ __launch_bounds__(THREADS, 1)
void vq_main(const float* __restrict__ x,
             const float* __restrict__ dict,
             float* __restrict__ out) {
    extern __shared__ char smem[];
    float*          sA    = (float*)(smem + OFF_SA);
    __half*         sAh   = (__half*)(smem + OFF_SAH);
    __half*         sBh   = (__half*)(smem + OFF_SBH);
    unsigned short* sCand = (unsigned short*)(smem + OFF_CAND);
    unsigned long long* rowBest = (unsigned long long*)(smem + OFF_BEST);
    float*          sNf   = (float*)(smem + OFF_NF);
    int*            sIdx  = (int*)(smem + OFF_IDX);

    const int t = threadIdx.x;
    const int j = t & 15;
    const int i = t >> 4;            // 0..31
    const size_t row0 = (size_t)blockIdx.x * MTILE;

    // Load x tile (float4, coalesced)
    {
        const float4* xv = (const float4*)(x + row0 * D_DIM);
        for (int e = t; e < MTILE * (D_DIM / 4); e += THREADS) {
            int r  = e >> 6;         // 64 float4 per row
            int c4 = e & 63;
            *(float4*)(sA + r * ASTRIDE + c4 * 4) = xv[r * 64 + c4];
        }
    }

    // Prefetch half-dict chunk 0 (32 d-rows x 128 codes = 8KB; 1 uint4/thread)
    uint4 pf;
    {
        int r = t >> 4, c16 = t & 15;             // 16 uint4 per d-row
        pf = ((const uint4*)g_dictH)[(size_t)r * (K_CODES / 8) + c16];
    }
    __syncthreads();

    // One-time: convert x tile to half (64 cvts/thread), per-row nf (exact
    // sequential fp32, load-bearing), init row winners.
    for (int e = t; e < MTILE * D_DIM; e += THREADS) {
        int r = e >> 8, d = e & 255;
        sAh[r * D_DIM + d] = __float2half_rn(sA[r * ASTRIDE + d]);
    }
    if (t < MTILE) {
        float s = 0.f;
        const float* rowp = sA + t * ASTRIDE;
        for (int d = 0; d < D_DIM; ++d)
            s = __fadd_rn(s, __fmul_rn(rowp[d], rowp[d]));
        sNf[t] = s;
        rowBest[t] = 0xFFFFFFFFFFFFFFFFull;
    }
    // Stage chunk 0 into buffer 0
    ((uint4*)sBh)[t] = pf;
    __syncthreads();

    // Screening state: 4 rows x 8 codes
    float cv[4][NCAND];
    unsigned short ci[4][NCAND];
    #pragma unroll
    for (int m = 0; m < 4; ++m)
        #pragma unroll
        for (int q = 0; q < NCAND; ++q) {
            cv[m][q] = __int_as_float(0x7f800000); ci[m][q] = 0;
        }
    float acc32[4][8];
    #pragma unroll
    for (int m = 0; m < 4; ++m)
        #pragma unroll
        for (int n = 0; n < 8; ++n) acc32[m][n] = 0.f;

    for (int c = 0; c < NCHUNK; ++c) {
        const int tt = c >> 3;
        const int kt = c & 7;
        const __half* sBuf = sBh + (c & 1) * (KCHUNK * NTILE);

        // Prefetch next chunk (overlapped with compute)
        if (c + 1 < NCHUNK) {
            const int base_d = ((c + 1) & 7) * KCHUNK;
            const int base_c = ((c + 1) >> 3) * NTILE;
            int r = t >> 4, c16 = t & 15;
            pf = ((const uint4*)g_dictH)[(size_t)(base_d + r) * (K_CODES / 8)
                                         + (base_c >> 3) + c16];
        }

        // HFMA2 screen: two 16-step windows, fp32 fold after each (fold-16
        // granularity is correctness-validated; do not widen).
        const int colbase = kt * KCHUNK;
        #pragma unroll
        for (int h = 0; h < 2; ++h) {
            __half2 aH[4][4];
            #pragma unroll
            for (int m = 0; m < 4; ++m)
                #pragma unroll
                for (int p = 0; p < 4; ++p) aH[m][p] = __float2half2_rn(0.f);

            #pragma unroll
            for (int kk = h * 16; kk < h * 16 + 16; ++kk) {
                __half2 a2[4];
                #pragma unroll
                for (int m = 0; m < 4; ++m)
                    a2[m] = __half2half2(sAh[(i + 32 * m) * D_DIM + colbase + kk]);
                uint4 braw = *(const uint4*)((const __half2*)(sBuf + kk * NTILE) + j * 4);
                __half2 b2[4];
                b2[0] = *(__half2*)&braw.x; b2[1] = *(__half2*)&braw.y;
                b2[2] = *(__half2*)&braw.z; b2[3] = *(__half2*)&braw.w;
                #pragma unroll
                for (int m = 0; m < 4; ++m)
                    #pragma unroll
                    for (int p = 0; p < 4; ++p)
                        aH[m][p] = __hfma2(a2[m], b2[p], aH[m][p]);
            }
            #pragma unroll
            for (int m = 0; m < 4; ++m)
                #pragma unroll
                for (int p = 0; p < 4; ++p) {
                    float2 s2 = __half22float2(aH[m][p]);
                    acc32[m][2 * p]     += s2.x;
                    acc32[m][2 * p + 1] += s2.y;
                }
        }

        // Publish prefetched chunk into the other buffer
        if (c + 1 < NCHUNK)
            ((uint4*)(sBh + ((c + 1) & 1) * (KCHUNK * NTILE)))[t] = pf;
        __syncthreads();

        if (kt == 7) {
            // Fold tile tt into per-row top-3 (ascending code order)
            const int cbase = tt * NTILE + j * 8;
            #pragma unroll
            for (int n = 0; n < 8; ++n) {
                const float ck = g_c[cbase + n];
                const unsigned short code = (unsigned short)(cbase + n);
                #pragma unroll
                for (int m = 0; m < 4; ++m) {
                    float v = ck - 2.f * acc32[m][n];
                    if (v < cv[m][2]) {
                        if (v < cv[m][1]) {
                            cv[m][2] = cv[m][1]; ci[m][2] = ci[m][1];
                            if (v < cv[m][0]) {
                                cv[m][1] = cv[m][0]; ci[m][1] = ci[m][0];
                                cv[m][0] = v;        ci[m][0] = code;
                            } else { cv[m][1] = v;   ci[m][1] = code; }
                        } else     { cv[m][2] = v;   ci[m][2] = code; }
                    }
                }
            }
            #pragma unroll
            for (int m = 0; m < 4; ++m)
                #pragma unroll
                for (int n = 0; n < 8; ++n) acc32[m][n] = 0.f;
        }
    }

    // Publish candidates
    #pragma unroll
    for (int m = 0; m < 4; ++m) {
        int r = i + 32 * m;
        #pragma unroll
        for (int q = 0; q < NCAND; ++q)
            sCand[r * CPR + j * NCAND + q] = ci[m][q];
    }
    __syncthreads();

    // Refine: EXACT reference arithmetic per candidate (4-way ILP).
    // Distances ~256 > 0 -> fp32 bit pattern is order-preserving in the
    // packed u64; low bits = code gives first-index tie-break via atomicMin.
    #pragma unroll 1
    for (int b = 0; b < TOTC / (THREADS * 4); ++b) {
        int rr[4], kk4[4];
        float s4[4] = {0.f, 0.f, 0.f, 0.f};
        #pragma unroll
        for (int u = 0; u < 4; ++u) {
            int id = t + THREADS * (4 * b + u);
            rr[u]  = id / CPR;
            kk4[u] = sCand[id];
        }
        for (int d = 0; d < D_DIM; d += 4) {
            #pragma unroll
            for (int u = 0; u < 4; ++u) {
                float4 dv = *(const float4*)(g_dictT + (size_t)kk4[u] * D_DIM + d);
                float4 xv = *(const float4*)(sA + rr[u] * ASTRIDE + d);
                float s = s4[u];
                s = fmaf(xv.x, dv.x, s);
                s = fmaf(xv.y, dv.y, s);
                s = fmaf(xv.z, dv.z, s);
                s = fmaf(xv.w, dv.w, s);
                s4[u] = s;
            }
        }
        #pragma unroll
        for (int u = 0; u < 4; ++u) {
            float t1 = __fadd_rn(sNf[rr[u]], g_c[kk4[u]]);
            float v  = __fsub_rn(t1, __fmul_rn(2.f, s4[u]));
            unsigned long long pk =
                ((unsigned long long)__float_as_uint(v) << 32) | (unsigned)kk4[u];
            atomicMin(&rowBest[rr[u]], pk);
        }
    }
    __syncthreads();

    if (t < MTILE) sIdx[t] = (int)(rowBest[t] & 0xFFFFFFFFull);
    __syncthreads();

    // Epilogue: gather q = 0.5*dictT[idx][d] (exact halving; coalesced),
    // write output, accumulate loss partial.
    float lsum = 0.f;
    for (int e = t; e < MTILE * D_DIM; e += THREADS) {
        int r = e >> 8;
        int d = e & 255;
        int idx = sIdx[r];
        float q  = 0.5f * g_dictT[(size_t)idx * D_DIM + d];
        float xv = sA[r * ASTRIDE + d];
        float df = xv - q;
        lsum = fmaf(df, df, lsum);
        out[(row0 + r) * D_DIM + d] = q;
    }

    #pragma unroll
    for (int o = 16; o > 0; o >>= 1)
        lsum += __shfl_xor_sync(0xffffffffu, lsum, o);
    float* sRed = (float*)sCand;          // reuse (candidates dead)
    __syncthreads();
    if ((t & 31) == 0) sRed[t >> 5] = lsum;
    __syncthreads();
    if (t == 0) {
        float s = 0.f;
        #pragma unroll
        for (int w = 0; w < THREADS / 32; ++w) s += sRed[w];
        atomicAdd(&g_loss, (double)s);
    }
}

// ---------------------------------------------------------------------------
// Kernel 3: loss = 1.25 * mean((x - q)^2)
// ---------------------------------------------------------------------------
__global__ void vq_finalize(float* __restrict__ out, int loss_idx) {
    out[loss_idx] = (float)(1.25 * g_loss * (1.0 / (double)(N_ROWS * D_DIM)));
}

extern "C" void kernel_launch(void* const* d_in, const int* in_sizes, int n_in,
                              void* d_out, int out_size) {
    const float* x    = (const float*)d_in[0];
    const float* dict = (const float*)d_in[1];
    float* out = (float*)d_out;

    cudaFuncSetAttribute(vq_main, cudaFuncAttributeMaxDynamicSharedMemorySize,
                         SMEM_BYTES);

    vq_transpose<<<dim3(K_CODES / 32, D_DIM / 32), 256>>>(dict);
    vq_tohalf<<<(D_DIM * K_CODES + 255) / 256, 256>>>(dict);
    vq_norms<<<(K_CODES + 255) / 256, 256>>>(dict);
    vq_main<<<N_ROWS / MTILE, THREADS, SMEM_BYTES>>>(x, dict, out);
    vq_finalize<<<1, 1>>>(out, out_size - 1);
}

// round 12
// speedup vs baseline: 3.0615x; 3.0615x over previous
#include <cuda_runtime.h>
#include <cuda_fp16.h>
#include <cstdint>

// Problem constants (fixed shapes):
//   x:          [16,64,64,256] fp32  -> N_ROWS=65536 rows of D_DIM=256
//   dictionary: [256,1024]     fp32  -> D_DIM x K_CODES
// Output: q_st (16777216 fp32) followed by loss (1 fp32).
//
// CORRECTNESS-CRITICAL (validated R6/R8/R9, rel_err 1.744171e-6, 0 flips):
//   approx screen -> per-row candidates -> EXACT fp32 reference arithmetic
//   replayed on candidates: sim = sequential fmaf chain over d=0..255;
//   t1 = fl(nf + c_k); v = fl(t1 - fl(2*sim)); first-index ties via packed
//   (bits<<32|code) atomicMin. nf/c_k are sequential fp32 square-sums in d
//   order. Do NOT alter refine-path order/roundings.
// Screen: warp-level mma.sync m16n8k16 (f16 in, f32 accum) — NO tcgen05 /
// mbarrier (4 consecutive container failures implicated that path). Top-12
// candidates per row (4 lanes x top-3), wider margin than prior screens.
#define D_DIM   256
#define K_CODES 1024
#define N_ROWS  65536
#define MTILE   128
#define THREADS 256
#define NTILES  8
#define BSTRIDE 264          // halfs per smem tile row (528B: LDSM conflict-free)
#define XSTRIDE 260          // fp32 x-tile stride for refine stage
#define NCAND   3
#define CPR     12
#define TOTC    (MTILE * CPR)   // 1536

// SMEM layout (bytes), total 211968 <= 227KB
#define OFF_AH    0            // x fp16, 128 x BSTRIDE        = 67584
#define OFF_B     67584        // dict fp16, 2 buffers         = 135168 (reused as fp32 x in refine)
#define OFF_C     202752       // c_k fp32 [1024]              = 4096
#define OFF_NF    206848       // nf fp32 [128]                = 512
#define OFF_CAND  207360       // u16 [1536]                   = 3072
#define OFF_BEST  210432       // u64 [128]                    = 1024
#define OFF_IDX   211456       // int [128]                    = 512
#define SMEM_BYTES 211968

__device__ float  g_dictT[K_CODES * D_DIM];
__device__ __half g_dictHT[K_CODES * D_DIM];
__device__ float  g_c[K_CODES];
__device__ double g_loss;

// ---- PTX helpers: only classic, hang-free primitives ----------------------
__device__ __forceinline__ uint32_t smem_u32(const void* p) {
    uint32_t a;
    asm("{ .reg .u64 t; cvta.to.shared.u64 t, %1; cvt.u32.u64 %0, t; }"
        : "=r"(a) : "l"(p));
    return a;
}
__device__ __forceinline__ void cp16(uint32_t dst, const void* src) {
    asm volatile("cp.async.cg.shared.global [%0], [%1], 16;"
                 :: "r"(dst), "l"(src) : "memory");
}
#define CP_COMMIT()  asm volatile("cp.async.commit_group;" ::: "memory")
#define CP_WAIT(n)   asm volatile("cp.async.wait_group %0;" :: "n"(n) : "memory")
__device__ __forceinline__ void ldsm4(uint32_t& r0, uint32_t& r1,
                                      uint32_t& r2, uint32_t& r3, uint32_t a) {
    asm volatile("ldmatrix.sync.aligned.m8n8.x4.shared.b16 {%0,%1,%2,%3}, [%4];"
                 : "=r"(r0), "=r"(r1), "=r"(r2), "=r"(r3) : "r"(a));
}
__device__ __forceinline__ void mma16816(float& c0, float& c1, float& c2,
                                         float& c3, const uint32_t a[4],
                                         uint32_t b0, uint32_t b1) {
    asm volatile(
        "mma.sync.aligned.m16n8k16.row.col.f32.f16.f16.f32 "
        "{%0,%1,%2,%3}, {%4,%5,%6,%7}, {%8,%9}, {%0,%1,%2,%3};"
        : "+f"(c0), "+f"(c1), "+f"(c2), "+f"(c3)
        : "r"(a[0]), "r"(a[1]), "r"(a[2]), "r"(a[3]), "r"(b0), "r"(b1));
}

// ---------------------------------------------------------------------------
// Prep 1: transpose dict[d][k] -> dictT[k][d] fp32 + fp16 (coalesced).
// ---------------------------------------------------------------------------
__global__ void vq_transpose(const float* __restrict__ dict) {
    __shared__ float tile[32][33];
    const int kb = blockIdx.x * 32, db = blockIdx.y * 32;
    const int tx = threadIdx.x & 31, ty = threadIdx.x >> 5;
    #pragma unroll
    for (int r = ty; r < 32; r += 8)
        tile[r][tx] = dict[(size_t)(db + r) * K_CODES + kb + tx];
    __syncthreads();
    #pragma unroll
    for (int r = ty; r < 32; r += 8) {
        float v = tile[tx][r];
        g_dictT[(size_t)(kb + r) * D_DIM + db + tx]  = v;
        g_dictHT[(size_t)(kb + r) * D_DIM + db + tx] = __float2half_rn(v);
    }
}
// ---------------------------------------------------------------------------
// Prep 2: c_k = sum_d fl(d*d), SEQUENTIAL fp32 adds in d order (load-bearing).
// ---------------------------------------------------------------------------
__global__ void vq_norms(const float* __restrict__ dict) {
    int k = blockIdx.x * blockDim.x + threadIdx.x;
    if (k == 0) g_loss = 0.0;
    if (k < K_CODES) {
        float c = 0.f;
        for (int d = 0; d < D_DIM; ++d) {
            float v = dict[(size_t)d * K_CODES + k];
            c = __fadd_rn(c, __fmul_rn(v, v));
        }
        g_c[k] = c;
    }
}

// cp.async one dict code-tile (128 codes x 256 halfs) into smem buffer.
__device__ __forceinline__ void load_b_tile(uint32_t sbase, int buf, int tt,
                                            int t) {
    const __half* src = g_dictHT + (size_t)tt * 128 * D_DIM;
    const uint32_t dstb = sbase + OFF_B + buf * (MTILE * BSTRIDE * 2);
    #pragma unroll
    for (int q = 0; q < 16; ++q) {
        int e   = t + THREADS * q;
        int row = e >> 5;            // 32 16B-blocks per row
        int c16 = e & 31;
        cp16(dstb + (uint32_t)(row * BSTRIDE + c16 * 8) * 2,
             src + (size_t)row * D_DIM + c16 * 8);
    }
}

// Top-3 insert (ascending-code scan order upstream keeps earliest on ties).
#define TOP3_INS(cv, ci, v, code)                                              \
    do {                                                                       \
        if ((v) < (cv)[2]) {                                                   \
            if ((v) < (cv)[1]) {                                               \
                (cv)[2] = (cv)[1]; (ci)[2] = (ci)[1];                          \
                if ((v) < (cv)[0]) { (cv)[1] = (cv)[0]; (ci)[1] = (ci)[0];     \
                                     (cv)[0] = (v);     (ci)[0] = (code); }    \
                else               { (cv)[1] = (v);     (ci)[1] = (code); }    \
            } else                 { (cv)[2] = (v);     (ci)[2] = (code); }    \
        }                                                                      \
    } while (0)

// ---------------------------------------------------------------------------
// Main: HMMA screen -> 12 cand/row -> exact refine -> gather/loss.
// ---------------------------------------------------------------------------
__global__ __launch_bounds__(THREADS, 1)
void vq_main(const float* __restrict__ x, float* __restrict__ out) {
    extern __shared__ char smem[];
    __half*         sAh   = (__half*)(smem + OFF_AH);
    float*          sC    = (float*)(smem + OFF_C);
    float*          sNf   = (float*)(smem + OFF_NF);
    unsigned short* sCand = (unsigned short*)(smem + OFF_CAND);
    unsigned long long* rowBest = (unsigned long long*)(smem + OFF_BEST);
    int*            sIdx  = (int*)(smem + OFF_IDX);
    float*          sX    = (float*)(smem + OFF_B);   // refine-phase overlay

    const int t = threadIdx.x;
    const int w = t >> 5;
    const int l = t & 31;
    const size_t row0 = (size_t)blockIdx.x * MTILE;
    const uint32_t sbase = smem_u32(smem);

    // Stage c_k
    #pragma unroll
    for (int q = 0; q < 4; ++q) sC[t + THREADS * q] = g_c[t + THREADS * q];

    // Load + convert x tile to fp16 (coalesced float4 loads)
    #pragma unroll
    for (int q = 0; q < 16; ++q) {
        int e  = t + THREADS * q;
        int r  = e >> 5;
        int d0 = (e & 31) * 8;
        const float4* xp = (const float4*)(x + (row0 + r) * D_DIM + d0);
        float4 v0 = xp[0], v1 = xp[1];
        __half2 h0 = __floats2half2_rn(v0.x, v0.y);
        __half2 h1 = __floats2half2_rn(v0.z, v0.w);
        __half2 h2 = __floats2half2_rn(v1.x, v1.y);
        __half2 h3 = __floats2half2_rn(v1.z, v1.w);
        uint4 pk;
        pk.x = *(uint32_t*)&h0; pk.y = *(uint32_t*)&h1;
        pk.z = *(uint32_t*)&h2; pk.w = *(uint32_t*)&h3;
        *(uint4*)((char*)sAh + (size_t)(r * BSTRIDE + d0) * 2) = pk;
    }

    // Start dict tiles 0 and 1 (cp.async groups g0, g1)
    load_b_tile(sbase, 0, 0, t); CP_COMMIT();
    load_b_tile(sbase, 1, 1, t); CP_COMMIT();

    // nf per row: EXACT sequential fp32 (load-bearing); init winners.
    if (t < MTILE) {
        float s = 0.f;
        const float* rowp = x + (row0 + t) * D_DIM;
        for (int d = 0; d < D_DIM; ++d)
            s = __fadd_rn(s, __fmul_rn(rowp[d], rowp[d]));
        sNf[t] = s;
        rowBest[t] = 0xFFFFFFFFFFFFFFFFull;
    }

    CP_WAIT(1);          // tile 0 landed
    __syncthreads();     // sAh + tile0 visible to all

    // A fragments for all K=256: afr[ks][0..3] (held in regs).
    // addr: row = w*16 + l%16, col = ks*16 + (l/16)*8 halfs.
    uint32_t afr[16][4];
    {
        uint32_t abase = sbase + OFF_AH
            + (uint32_t)((w * 16 + (l & 15)) * BSTRIDE + (l >> 4) * 8) * 2;
        #pragma unroll
        for (int ks = 0; ks < 16; ++ks)
            ldsm4(afr[ks][0], afr[ks][1], afr[ks][2], afr[ks][3],
                  abase + ks * 32);
    }

    // Per-lane top-3 for two rows: rA = w*16 + l/4, rB = rA + 8.
    float cvA[NCAND], cvB[NCAND];
    unsigned short ciA[NCAND], ciB[NCAND];
    #pragma unroll
    for (int q = 0; q < NCAND; ++q) {
        cvA[q] = __int_as_float(0x7f800000); ciA[q] = 0;
        cvB[q] = __int_as_float(0x7f800000); ciB[q] = 0;
    }

    for (int tt = 0; tt < NTILES; ++tt) {
        const uint32_t bbase = sbase + OFF_B + (tt & 1) * (MTILE * BSTRIDE * 2);
        #pragma unroll
        for (int n = 0; n < 16; ++n) {
            // B frags for all 16 ksteps: 8x ldmatrix.x4
            // addr: coderow = n*8 + l%8, col = g*32 + (l/8)*8 halfs.
            uint32_t bfr[16][2];
            const uint32_t bb = bbase
                + (uint32_t)((n * 8 + (l & 7)) * BSTRIDE + (l >> 3) * 8) * 2;
            #pragma unroll
            for (int g = 0; g < 8; ++g)
                ldsm4(bfr[2 * g][0], bfr[2 * g][1],
                      bfr[2 * g + 1][0], bfr[2 * g + 1][1], bb + g * 64);

            float c0 = 0.f, c1 = 0.f, c2 = 0.f, c3 = 0.f;
            #pragma unroll
            for (int ks = 0; ks < 16; ++ks)
                mma16816(c0, c1, c2, c3, afr[ks], bfr[ks][0], bfr[ks][1]);

            // Fold: lane codes cb, cb+1; rows rA (c0,c1) and rB (c2,c3).
            const int cb = tt * 128 + n * 8 + (l & 3) * 2;
            float ck0 = sC[cb], ck1 = sC[cb + 1];
            float vA0 = ck0 - 2.f * c0, vA1 = ck1 - 2.f * c1;
            float vB0 = ck0 - 2.f * c2, vB1 = ck1 - 2.f * c3;
            TOP3_INS(cvA, ciA, vA0, (unsigned short)cb);
            TOP3_INS(cvA, ciA, vA1, (unsigned short)(cb + 1));
            TOP3_INS(cvB, ciB, vB0, (unsigned short)cb);
            TOP3_INS(cvB, ciB, vB1, (unsigned short)(cb + 1));
        }
        __syncthreads();                     // done reading buf tt&1
        if (tt + 2 < NTILES) {
            load_b_tile(sbase, tt & 1, tt + 2, t); CP_COMMIT();
            CP_WAIT(1);                      // tile tt+1 landed
            __syncthreads();
        } else if (tt + 1 < NTILES) {
            CP_WAIT(0);                      // last tile landed
            __syncthreads();
        }
    }

    // Publish candidates: 4 lanes x top-3 = 12 per row.
    {
        int rA = w * 16 + (l >> 2);
        int rB = rA + 8;
        #pragma unroll
        for (int q = 0; q < NCAND; ++q) {
            sCand[rA * CPR + (l & 3) * NCAND + q] = ciA[q];
            sCand[rB * CPR + (l & 3) * NCAND + q] = ciB[q];
        }
    }
    __syncthreads();

    // Stage x tile as fp32 into the dead B buffers (coalesced).
    #pragma unroll
    for (int q = 0; q < 32; ++q) {
        int e  = t + THREADS * q;           // 8192 float4 blocks
        int r  = e >> 6;
        int c4 = e & 63;
        *(float4*)(sX + r * XSTRIDE + c4 * 4) =
            *(const float4*)(x + (row0 + r) * D_DIM + c4 * 4);
    }
    __syncthreads();

    // Refine: thread t owns row t>>1, candidates (t&1)*6..+5. EXACT chains.
    {
        const int r = t >> 1;
        const float* xr = sX + r * XSTRIDE;
        int   kk[6];
        float s6[6] = {0.f, 0.f, 0.f, 0.f, 0.f, 0.f};
        #pragma unroll
        for (int u = 0; u < 6; ++u)
            kk[u] = sCand[r * CPR + (t & 1) * 6 + u];
        for (int d = 0; d < D_DIM; d += 4) {
            float4 xv = *(const float4*)(xr + d);
            #pragma unroll
            for (int u = 0; u < 6; ++u) {
                float4 dv = *(const float4*)(g_dictT + (size_t)kk[u] * D_DIM + d);
                float s = s6[u];
                s = fmaf(xv.x, dv.x, s);
                s = fmaf(xv.y, dv.y, s);
                s = fmaf(xv.z, dv.z, s);
                s = fmaf(xv.w, dv.w, s);
                s6[u] = s;
            }
        }
        const float nf = sNf[r];
        #pragma unroll
        for (int u = 0; u < 6; ++u) {
            float t1 = __fadd_rn(nf, sC[kk[u]]);
            float v  = __fsub_rn(t1, __fmul_rn(2.f, s6[u]));
            unsigned long long pk =
                ((unsigned long long)__float_as_uint(v) << 32) | (unsigned)kk[u];
            atomicMin(&rowBest[r], pk);
        }
    }
    __syncthreads();
    if (t < MTILE) sIdx[t] = (int)(rowBest[t] & 0xFFFFFFFFull);
    __syncthreads();

    // Epilogue: q = 0.5*dictT[idx][d] (exact), write out, loss partial.
    float lsum = 0.f;
    for (int e = t; e < MTILE * D_DIM; e += THREADS) {
        int r = e >> 8, d = e & 255;
        int idx = sIdx[r];
        float q  = 0.5f * g_dictT[(size_t)idx * D_DIM + d];
        float xv = sX[r * XSTRIDE + d];
        float df = xv - q;
        lsum = fmaf(df, df, lsum);
        out[(row0 + r) * D_DIM + d] = q;
    }
    #pragma unroll
    for (int o = 16; o > 0; o >>= 1)
        lsum += __shfl_xor_sync(0xffffffffu, lsum, o);
    float* sRed = (float*)sCand;     // candidates dead; reuse
    __syncthreads();
    if (l == 0) sRed[w] = lsum;
    __syncthreads();
    if (t == 0) {
        float s = 0.f;
        #pragma unroll
        for (int ww = 0; ww < THREADS / 32; ++ww) s += sRed[ww];
        atomicAdd(&g_loss, (double)s);
    }
}

// ---------------------------------------------------------------------------
// loss = 1.25 * mean((x - q)^2)
// ---------------------------------------------------------------------------
__global__ void vq_finalize(float* __restrict__ out, int loss_idx) {
    out[loss_idx] = (float)(1.25 * g_loss * (1.0 / (double)(N_ROWS * D_DIM)));
}

extern "C" void kernel_launch(void* const* d_in, const int* in_sizes, int n_in,
                              void* d_out, int out_size) {
    const float* x    = (const float*)d_in[0];
    const float* dict = (const float*)d_in[1];
    float* out = (float*)d_out;

    cudaFuncSetAttribute(vq_main, cudaFuncAttributeMaxDynamicSharedMemorySize,
                         SMEM_BYTES);

    vq_transpose<<<dim3(K_CODES / 32, D_DIM / 32), 256>>>(dict);
    vq_norms<<<(K_CODES + 255) / 256, 256>>>(dict);
    vq_main<<<N_ROWS / MTILE, THREADS, SMEM_BYTES>>>(x, out);
    vq_finalize<<<1, 1>>>(out, out_size - 1);
}

// round 13
// speedup vs baseline: 3.1357x; 1.0242x over previous
#include <cuda_runtime.h>
#include <cuda_fp16.h>
#include <cstdint>

// Problem constants (fixed shapes):
//   x:          [16,64,64,256] fp32  -> N_ROWS=65536 rows of D_DIM=256
//   dictionary: [256,1024]     fp32  -> D_DIM x K_CODES
// Output: q_st (16777216 fp32) followed by loss (1 fp32).
//
// CORRECTNESS-CRITICAL (validated R6/R8/R12, rel_err 1.744171e-6, 0 flips):
//   approx screen -> per-row candidates -> EXACT fp32 reference arithmetic
//   replayed on candidates: sim = sequential fmaf chain over d=0..255;
//   t1 = fl(nf + c_k); v = fl(t1 - fl(2*sim)); first-index ties via packed
//   (bits<<32|code) atomicMin. nf/c_k are sequential fp32 square-sums in d
//   order. Do NOT alter refine-path order/roundings.
// Screen: warp-level mma.sync m16n8k16 (f16 in, f32 accum), top-12 cand/row.
// R13 change (perf-only): 4 independent k-accumulator sets per n-tile to
// break the 16-deep serial HMMA dependency chain (screen is order-free).
#define D_DIM   256
#define K_CODES 1024
#define N_ROWS  65536
#define MTILE   128
#define THREADS 256
#define NTILES  8
#define BSTRIDE 264          // halfs per smem tile row (528B: LDSM conflict-free)
#define XSTRIDE 260          // fp32 x-tile stride for refine stage
#define NCAND   3
#define CPR     12
#define TOTC    (MTILE * CPR)   // 1536

// SMEM layout (bytes), total 211968 <= 227KB
#define OFF_AH    0            // x fp16, 128 x BSTRIDE        = 67584
#define OFF_B     67584        // dict fp16, 2 buffers         = 135168 (reused as fp32 x in refine)
#define OFF_C     202752       // c_k fp32 [1024]              = 4096
#define OFF_NF    206848       // nf fp32 [128]                = 512
#define OFF_CAND  207360       // u16 [1536]                   = 3072
#define OFF_BEST  210432       // u64 [128]                    = 1024
#define OFF_IDX   211456       // int [128]                    = 512
#define SMEM_BYTES 211968

__device__ float  g_dictT[K_CODES * D_DIM];
__device__ __half g_dictHT[K_CODES * D_DIM];
__device__ float  g_c[K_CODES];
__device__ double g_loss;

// ---- PTX helpers: only classic, hang-free primitives ----------------------
__device__ __forceinline__ uint32_t smem_u32(const void* p) {
    uint32_t a;
    asm("{ .reg .u64 t; cvta.to.shared.u64 t, %1; cvt.u32.u64 %0, t; }"
        : "=r"(a) : "l"(p));
    return a;
}
__device__ __forceinline__ void cp16(uint32_t dst, const void* src) {
    asm volatile("cp.async.cg.shared.global [%0], [%1], 16;"
                 :: "r"(dst), "l"(src) : "memory");
}
#define CP_COMMIT()  asm volatile("cp.async.commit_group;" ::: "memory")
#define CP_WAIT(n)   asm volatile("cp.async.wait_group %0;" :: "n"(n) : "memory")
__device__ __forceinline__ void ldsm4(uint32_t& r0, uint32_t& r1,
                                      uint32_t& r2, uint32_t& r3, uint32_t a) {
    asm volatile("ldmatrix.sync.aligned.m8n8.x4.shared.b16 {%0,%1,%2,%3}, [%4];"
                 : "=r"(r0), "=r"(r1), "=r"(r2), "=r"(r3) : "r"(a));
}
__device__ __forceinline__ void mma16816(float& c0, float& c1, float& c2,
                                         float& c3, const uint32_t a[4],
                                         uint32_t b0, uint32_t b1) {
    asm volatile(
        "mma.sync.aligned.m16n8k16.row.col.f32.f16.f16.f32 "
        "{%0,%1,%2,%3}, {%4,%5,%6,%7}, {%8,%9}, {%0,%1,%2,%3};"
        : "+f"(c0), "+f"(c1), "+f"(c2), "+f"(c3)
        : "r"(a[0]), "r"(a[1]), "r"(a[2]), "r"(a[3]), "r"(b0), "r"(b1));
}

// ---------------------------------------------------------------------------
// Prep 1: transpose dict[d][k] -> dictT[k][d] fp32 + fp16 (coalesced).
// ---------------------------------------------------------------------------
__global__ void vq_transpose(const float* __restrict__ dict) {
    __shared__ float tile[32][33];
    const int kb = blockIdx.x * 32, db = blockIdx.y * 32;
    const int tx = threadIdx.x & 31, ty = threadIdx.x >> 5;
    #pragma unroll
    for (int r = ty; r < 32; r += 8)
        tile[r][tx] = dict[(size_t)(db + r) * K_CODES + kb + tx];
    __syncthreads();
    #pragma unroll
    for (int r = ty; r < 32; r += 8) {
        float v = tile[tx][r];
        g_dictT[(size_t)(kb + r) * D_DIM + db + tx]  = v;
        g_dictHT[(size_t)(kb + r) * D_DIM + db + tx] = __float2half_rn(v);
    }
}
// ---------------------------------------------------------------------------
// Prep 2: c_k = sum_d fl(d*d), SEQUENTIAL fp32 adds in d order (load-bearing).
// ---------------------------------------------------------------------------
__global__ void vq_norms(const float* __restrict__ dict) {
    int k = blockIdx.x * blockDim.x + threadIdx.x;
    if (k == 0) g_loss = 0.0;
    if (k < K_CODES) {
        float c = 0.f;
        for (int d = 0; d < D_DIM; ++d) {
            float v = dict[(size_t)d * K_CODES + k];
            c = __fadd_rn(c, __fmul_rn(v, v));
        }
        g_c[k] = c;
    }
}

// cp.async one dict code-tile (128 codes x 256 halfs) into smem buffer.
__device__ __forceinline__ void load_b_tile(uint32_t sbase, int buf, int tt,
                                            int t) {
    const __half* src = g_dictHT + (size_t)tt * 128 * D_DIM;
    const uint32_t dstb = sbase + OFF_B + buf * (MTILE * BSTRIDE * 2);
    #pragma unroll
    for (int q = 0; q < 16; ++q) {
        int e   = t + THREADS * q;
        int row = e >> 5;            // 32 16B-blocks per row
        int c16 = e & 31;
        cp16(dstb + (uint32_t)(row * BSTRIDE + c16 * 8) * 2,
             src + (size_t)row * D_DIM + c16 * 8);
    }
}

// Top-3 insert (ascending-code scan order upstream keeps earliest on ties).
#define TOP3_INS(cv, ci, v, code)                                              \
    do {                                                                       \
        if ((v) < (cv)[2]) {                                                   \
            if ((v) < (cv)[1]) {                                               \
                (cv)[2] = (cv)[1]; (ci)[2] = (ci)[1];                          \
                if ((v) < (cv)[0]) { (cv)[1] = (cv)[0]; (ci)[1] = (ci)[0];     \
                                     (cv)[0] = (v);     (ci)[0] = (code); }    \
                else               { (cv)[1] = (v);     (ci)[1] = (code); }    \
            } else                 { (cv)[2] = (v);     (ci)[2] = (code); }    \
        }                                                                      \
    } while (0)

// ---------------------------------------------------------------------------
// Main: HMMA screen -> 12 cand/row -> exact refine -> gather/loss.
// ---------------------------------------------------------------------------
__global__ __launch_bounds__(THREADS, 1)
void vq_main(const float* __restrict__ x, float* __restrict__ out) {
    extern __shared__ char smem[];
    __half*         sAh   = (__half*)(smem + OFF_AH);
    float*          sC    = (float*)(smem + OFF_C);
    float*          sNf   = (float*)(smem + OFF_NF);
    unsigned short* sCand = (unsigned short*)(smem + OFF_CAND);
    unsigned long long* rowBest = (unsigned long long*)(smem + OFF_BEST);
    int*            sIdx  = (int*)(smem + OFF_IDX);
    float*          sX    = (float*)(smem + OFF_B);   // refine-phase overlay

    const int t = threadIdx.x;
    const int w = t >> 5;
    const int l = t & 31;
    const size_t row0 = (size_t)blockIdx.x * MTILE;
    const uint32_t sbase = smem_u32(smem);

    // Stage c_k
    #pragma unroll
    for (int q = 0; q < 4; ++q) sC[t + THREADS * q] = g_c[t + THREADS * q];

    // Load + convert x tile to fp16 (coalesced float4 loads)
    #pragma unroll
    for (int q = 0; q < 16; ++q) {
        int e  = t + THREADS * q;
        int r  = e >> 5;
        int d0 = (e & 31) * 8;
        const float4* xp = (const float4*)(x + (row0 + r) * D_DIM + d0);
        float4 v0 = xp[0], v1 = xp[1];
        __half2 h0 = __floats2half2_rn(v0.x, v0.y);
        __half2 h1 = __floats2half2_rn(v0.z, v0.w);
        __half2 h2 = __floats2half2_rn(v1.x, v1.y);
        __half2 h3 = __floats2half2_rn(v1.z, v1.w);
        uint4 pk;
        pk.x = *(uint32_t*)&h0; pk.y = *(uint32_t*)&h1;
        pk.z = *(uint32_t*)&h2; pk.w = *(uint32_t*)&h3;
        *(uint4*)((char*)sAh + (size_t)(r * BSTRIDE + d0) * 2) = pk;
    }

    // Start dict tiles 0 and 1 (cp.async groups g0, g1)
    load_b_tile(sbase, 0, 0, t); CP_COMMIT();
    load_b_tile(sbase, 1, 1, t); CP_COMMIT();

    // nf per row: EXACT sequential fp32 (load-bearing); init winners.
    if (t < MTILE) {
        float s = 0.f;
        const float* rowp = x + (row0 + t) * D_DIM;
        for (int d = 0; d < D_DIM; ++d)
            s = __fadd_rn(s, __fmul_rn(rowp[d], rowp[d]));
        sNf[t] = s;
        rowBest[t] = 0xFFFFFFFFFFFFFFFFull;
    }

    CP_WAIT(1);          // tile 0 landed
    __syncthreads();     // sAh + tile0 visible to all

    // A fragments for all K=256: afr[ks][0..3] (held in regs).
    // addr: row = w*16 + l%16, col = ks*16 + (l/16)*8 halfs.
    uint32_t afr[16][4];
    {
        uint32_t abase = sbase + OFF_AH
            + (uint32_t)((w * 16 + (l & 15)) * BSTRIDE + (l >> 4) * 8) * 2;
        #pragma unroll
        for (int ks = 0; ks < 16; ++ks)
            ldsm4(afr[ks][0], afr[ks][1], afr[ks][2], afr[ks][3],
                  abase + ks * 32);
    }

    // Per-lane top-3 for two rows: rA = w*16 + l/4, rB = rA + 8.
    float cvA[NCAND], cvB[NCAND];
    unsigned short ciA[NCAND], ciB[NCAND];
    #pragma unroll
    for (int q = 0; q < NCAND; ++q) {
        cvA[q] = __int_as_float(0x7f800000); ciA[q] = 0;
        cvB[q] = __int_as_float(0x7f800000); ciB[q] = 0;
    }

    for (int tt = 0; tt < NTILES; ++tt) {
        const uint32_t bbase = sbase + OFF_B + (tt & 1) * (MTILE * BSTRIDE * 2);
        #pragma unroll 2
        for (int n = 0; n < 16; ++n) {
            // B frags for all 16 ksteps: 8x ldmatrix.x4
            uint32_t bfr[16][2];
            const uint32_t bb = bbase
                + (uint32_t)((n * 8 + (l & 7)) * BSTRIDE + (l >> 3) * 8) * 2;
            #pragma unroll
            for (int g = 0; g < 8; ++g)
                ldsm4(bfr[2 * g][0], bfr[2 * g][1],
                      bfr[2 * g + 1][0], bfr[2 * g + 1][1], bb + g * 64);

            // R13: 4 independent accumulator sets -> 4 MMA chains in flight
            // (screen is order-free; refine below is the exact path).
            float acc[4][4];
            #pragma unroll
            for (int s = 0; s < 4; ++s)
                #pragma unroll
                for (int e = 0; e < 4; ++e) acc[s][e] = 0.f;
            #pragma unroll
            for (int ks = 0; ks < 16; ++ks)
                mma16816(acc[ks & 3][0], acc[ks & 3][1],
                         acc[ks & 3][2], acc[ks & 3][3],
                         afr[ks], bfr[ks][0], bfr[ks][1]);
            float c0 = (acc[0][0] + acc[1][0]) + (acc[2][0] + acc[3][0]);
            float c1 = (acc[0][1] + acc[1][1]) + (acc[2][1] + acc[3][1]);
            float c2 = (acc[0][2] + acc[1][2]) + (acc[2][2] + acc[3][2]);
            float c3 = (acc[0][3] + acc[1][3]) + (acc[2][3] + acc[3][3]);

            // Fold: lane codes cb, cb+1; rows rA (c0,c1) and rB (c2,c3).
            const int cb = tt * 128 + n * 8 + (l & 3) * 2;
            float ck0 = sC[cb], ck1 = sC[cb + 1];
            float vA0 = ck0 - 2.f * c0, vA1 = ck1 - 2.f * c1;
            float vB0 = ck0 - 2.f * c2, vB1 = ck1 - 2.f * c3;
            TOP3_INS(cvA, ciA, vA0, (unsigned short)cb);
            TOP3_INS(cvA, ciA, vA1, (unsigned short)(cb + 1));
            TOP3_INS(cvB, ciB, vB0, (unsigned short)cb);
            TOP3_INS(cvB, ciB, vB1, (unsigned short)(cb + 1));
        }
        __syncthreads();                     // done reading buf tt&1
        if (tt + 2 < NTILES) {
            load_b_tile(sbase, tt & 1, tt + 2, t); CP_COMMIT();
            CP_WAIT(1);                      // tile tt+1 landed
            __syncthreads();
        } else if (tt + 1 < NTILES) {
            CP_WAIT(0);                      // last tile landed
            __syncthreads();
        }
    }

    // Publish candidates: 4 lanes x top-3 = 12 per row.
    {
        int rA = w * 16 + (l >> 2);
        int rB = rA + 8;
        #pragma unroll
        for (int q = 0; q < NCAND; ++q) {
            sCand[rA * CPR + (l & 3) * NCAND + q] = ciA[q];
            sCand[rB * CPR + (l & 3) * NCAND + q] = ciB[q];
        }
    }
    __syncthreads();

    // Stage x tile as fp32 into the dead B buffers (coalesced).
    #pragma unroll
    for (int q = 0; q < 32; ++q) {
        int e  = t + THREADS * q;           // 8192 float4 blocks
        int r  = e >> 6;
        int c4 = e & 63;
        *(float4*)(sX + r * XSTRIDE + c4 * 4) =
            *(const float4*)(x + (row0 + r) * D_DIM + c4 * 4);
    }
    __syncthreads();

    // Refine: thread t owns row t>>1, candidates (t&1)*6..+5. EXACT chains.
    {
        const int r = t >> 1;
        const float* xr = sX + r * XSTRIDE;
        int   kk[6];
        float s6[6] = {0.f, 0.f, 0.f, 0.f, 0.f, 0.f};
        #pragma unroll
        for (int u = 0; u < 6; ++u)
            kk[u] = sCand[r * CPR + (t & 1) * 6 + u];
        for (int d = 0; d < D_DIM; d += 4) {
            float4 xv = *(const float4*)(xr + d);
            #pragma unroll
            for (int u = 0; u < 6; ++u) {
                float4 dv = *(const float4*)(g_dictT + (size_t)kk[u] * D_DIM + d);
                float s = s6[u];
                s = fmaf(xv.x, dv.x, s);
                s = fmaf(xv.y, dv.y, s);
                s = fmaf(xv.z, dv.z, s);
                s = fmaf(xv.w, dv.w, s);
                s6[u] = s;
            }
        }
        const float nf = sNf[r];
        #pragma unroll
        for (int u = 0; u < 6; ++u) {
            float t1 = __fadd_rn(nf, sC[kk[u]]);
            float v  = __fsub_rn(t1, __fmul_rn(2.f, s6[u]));
            unsigned long long pk =
                ((unsigned long long)__float_as_uint(v) << 32) | (unsigned)kk[u];
            atomicMin(&rowBest[r], pk);
        }
    }
    __syncthreads();
    if (t < MTILE) sIdx[t] = (int)(rowBest[t] & 0xFFFFFFFFull);
    __syncthreads();

    // Epilogue: q = 0.5*dictT[idx][d] (exact), write out, loss partial.
    float lsum = 0.f;
    for (int e = t; e < MTILE * D_DIM; e += THREADS) {
        int r = e >> 8, d = e & 255;
        int idx = sIdx[r];
        float q  = 0.5f * g_dictT[(size_t)idx * D_DIM + d];
        float xv = sX[r * XSTRIDE + d];
        float df = xv - q;
        lsum = fmaf(df, df, lsum);
        out[(row0 + r) * D_DIM + d] = q;
    }
    #pragma unroll
    for (int o = 16; o > 0; o >>= 1)
        lsum += __shfl_xor_sync(0xffffffffu, lsum, o);
    float* sRed = (float*)sCand;     // candidates dead; reuse
    __syncthreads();
    if (l == 0) sRed[w] = lsum;
    __syncthreads();
    if (t == 0) {
        float s = 0.f;
        #pragma unroll
        for (int ww = 0; ww < THREADS / 32; ++ww) s += sRed[ww];
        atomicAdd(&g_loss, (double)s);
    }
}

// ---------------------------------------------------------------------------
// loss = 1.25 * mean((x - q)^2)
// ---------------------------------------------------------------------------
__global__ void vq_finalize(float* __restrict__ out, int loss_idx) {
    out[loss_idx] = (float)(1.25 * g_loss * (1.0 / (double)(N_ROWS * D_DIM)));
}

extern "C" void kernel_launch(void* const* d_in, const int* in_sizes, int n_in,
                              void* d_out, int out_size) {
    const float* x    = (const float*)d_in[0];
    const float* dict = (const float*)d_in[1];
    float* out = (float*)d_out;

    cudaFuncSetAttribute(vq_main, cudaFuncAttributeMaxDynamicSharedMemorySize,
                         SMEM_BYTES);

    vq_transpose<<<dim3(K_CODES / 32, D_DIM / 32), 256>>>(dict);
    vq_norms<<<(K_CODES + 255) / 256, 256>>>(dict);
    vq_main<<<N_ROWS / MTILE, THREADS, SMEM_BYTES>>>(x, out);
    vq_finalize<<<1, 1>>>(out, out_size - 1);
}